// round 3
// baseline (speedup 1.0000x reference)
#include <cuda_runtime.h>
#include <math.h>

#define SEQ   1024
#define EMB   1024
#define BATCH 2
#define MHEAD 16      // total heads (M*H)
#define HD    64      // head dim
#define E3    (3*EMB)

// ---------------- scratch (allocation-free rule: __device__ globals) --------
__device__ float g_qkv[(size_t)BATCH*SEQ*E3];       // [2048][3072]  q|k|v
__device__ float g_att[(size_t)BATCH*MHEAD*SEQ*SEQ]; // att, then p in-place
__device__ float g_ao [(size_t)BATCH*SEQ*EMB];       // attention out pre-proj

// ---------------- generic NT sgemm: C[M][N] = A[M][K] @ B[N][K]^T -----------
// row-major everywhere; M,N,K multiples of 64/64/16. 256 threads, 4x4 micro.
template<int BM, int BN, int BK>
__global__ void gemm_nt(const float* __restrict__ A, const float* __restrict__ B,
                        float* __restrict__ C, int Mo, int N, int K) {
    __shared__ float As[BK][BM + 1];
    __shared__ float Bs[BK][BN + 1];
    const int bm = blockIdx.y * BM, bn = blockIdx.x * BN;
    const int tid = threadIdx.x;
    const int tx = tid & 15, ty = tid >> 4;
    float acc[4][4] = {};
    for (int kt = 0; kt < K; kt += BK) {
        #pragma unroll
        for (int i = tid; i < BM * BK; i += 256) {
            int r = i / BK, c = i % BK;
            As[c][r] = A[(size_t)(bm + r) * K + kt + c];
        }
        #pragma unroll
        for (int i = tid; i < BN * BK; i += 256) {
            int r = i / BK, c = i % BK;
            Bs[c][r] = B[(size_t)(bn + r) * K + kt + c];
        }
        __syncthreads();
        #pragma unroll
        for (int k = 0; k < BK; k++) {
            float ra[4], rb[4];
            #pragma unroll
            for (int a = 0; a < 4; a++) ra[a] = As[k][ty + 16 * a];
            #pragma unroll
            for (int b = 0; b < 4; b++) rb[b] = Bs[k][tx + 16 * b];
            #pragma unroll
            for (int a = 0; a < 4; a++)
                #pragma unroll
                for (int b = 0; b < 4; b++) acc[a][b] += ra[a] * rb[b];
        }
        __syncthreads();
    }
    #pragma unroll
    for (int a = 0; a < 4; a++)
        #pragma unroll
        for (int b = 0; b < 4; b++)
            C[(size_t)(bm + ty + 16 * a) * N + bn + tx + 16 * b] = acc[a][b];
}

// ---------------- scores: att = mask(QK^T/64); arc = sigmoid(att) -----------
// grid: (S/64 key tiles, S/64 query tiles, B*MHEAD)
__global__ void att_kernel(const int* __restrict__ mask_head,
                           const int* __restrict__ mask_child,
                           float* __restrict__ arc) {
    const int bh   = blockIdx.z;          // b*16 + head
    const int b    = bh >> 4;
    const int head = bh & 15;
    const int grp  = head >> 3;           // 0 -> mask_head, 1 -> mask_child
    const int q0 = blockIdx.y * 64, k0 = blockIdx.x * 64;
    const int tid = threadIdx.x;
    const int tx = tid & 15, ty = tid >> 4;

    float* attp = g_att + (size_t)bh * SEQ * SEQ;
    float* arcp = arc ? arc + (size_t)bh * SEQ * SEQ : nullptr;

    if (k0 > q0 + 63) {  // fully above causal diagonal
        #pragma unroll
        for (int a = 0; a < 4; a++)
            #pragma unroll
            for (int c = 0; c < 4; c++) {
                size_t idx = (size_t)(q0 + ty + 16 * a) * SEQ + (k0 + tx + 16 * c);
                attp[idx] = -INFINITY;
                if (arcp) arcp[idx] = 0.0f;
            }
        return;
    }

    __shared__ float Qs[HD][65];
    __shared__ float Ks[HD][65];
    const float* qbase = g_qkv + ((size_t)b * SEQ + q0) * E3 + head * HD;
    const float* kbase = g_qkv + ((size_t)b * SEQ + k0) * E3 + EMB + head * HD;
    #pragma unroll
    for (int i = tid; i < 64 * HD; i += 256) {
        int r = i >> 6, c = i & 63;
        Qs[c][r] = qbase[(size_t)r * E3 + c];
        Ks[c][r] = kbase[(size_t)r * E3 + c];
    }
    __syncthreads();

    float acc[4][4] = {};
    #pragma unroll
    for (int k = 0; k < HD; k++) {
        float ra[4], rb[4];
        #pragma unroll
        for (int a = 0; a < 4; a++) ra[a] = Qs[k][ty + 16 * a];
        #pragma unroll
        for (int c = 0; c < 4; c++) rb[c] = Ks[k][tx + 16 * c];
        #pragma unroll
        for (int a = 0; a < 4; a++)
            #pragma unroll
            for (int c = 0; c < 4; c++) acc[a][c] += ra[a] * rb[c];
    }

    const int* msk = (grp == 0 ? mask_head : mask_child) + (size_t)b * SEQ * SEQ;
    #pragma unroll
    for (int a = 0; a < 4; a++) {
        int qi = q0 + ty + 16 * a;
        #pragma unroll
        for (int c = 0; c < 4; c++) {
            int kj = k0 + tx + 16 * c;
            float val = acc[a][c] * (1.0f / 64.0f);   // scaled twice by d^-0.5
            bool valid = (kj <= qi) && (msk[(size_t)qi * SEQ + kj] != 0);
            size_t idx = (size_t)qi * SEQ + kj;
            attp[idx] = valid ? val : -INFINITY;
            if (arcp) arcp[idx] = valid ? 1.0f / (1.0f + __expf(-val)) : 0.0f;
        }
    }
}

// ---------------- softmax over rows (in-place on g_att) ---------------------
__global__ void softmax_kernel() {
    const int row = blockIdx.x;                // 0..B*MHEAD*SEQ-1
    float* p = g_att + (size_t)row * SEQ;
    const int tid = threadIdx.x;               // 256
    float v[4];
    float mx = -INFINITY;
    #pragma unroll
    for (int i = 0; i < 4; i++) { v[i] = p[tid + 256 * i]; mx = fmaxf(mx, v[i]); }
    __shared__ float red[256];
    red[tid] = mx; __syncthreads();
    for (int s = 128; s > 0; s >>= 1) {
        if (tid < s) red[tid] = fmaxf(red[tid], red[tid + s]);
        __syncthreads();
    }
    mx = red[0]; __syncthreads();
    if (mx == -INFINITY) {                     // fully-masked row (defensive)
        #pragma unroll
        for (int i = 0; i < 4; i++) p[tid + 256 * i] = 0.0f;
        return;
    }
    float sum = 0.0f;
    #pragma unroll
    for (int i = 0; i < 4; i++) { v[i] = __expf(v[i] - mx); sum += v[i]; }
    red[tid] = sum; __syncthreads();
    for (int s = 128; s > 0; s >>= 1) {
        if (tid < s) red[tid] += red[tid + s];
        __syncthreads();
    }
    float inv = 1.0f / red[0];
    #pragma unroll
    for (int i = 0; i < 4; i++) p[tid + 256 * i] = v[i] * inv;
}

// ---------------- PV: ao[b,q,head*64+c] = sum_k p[q,k] * v[k,c] -------------
// grid: (S/64 query tiles, B*MHEAD). Causal: only K tiles kt <= qt contribute.
__global__ void pv_kernel() {
    const int bh = blockIdx.y;
    const int b = bh >> 4, head = bh & 15;
    const int qt = blockIdx.x;
    const int tid = threadIdx.x;
    const int tx = tid & 15, ty = tid >> 4;

    const float* p = g_att + (size_t)bh * SEQ * SEQ + (size_t)qt * 64 * SEQ;
    const float* vbase = g_qkv + (size_t)b * SEQ * E3 + 2 * EMB + head * HD;

    __shared__ float Ps[64][65];
    __shared__ float Vs[64][65];
    float acc[4][4] = {};
    for (int kt = 0; kt <= qt; kt++) {
        #pragma unroll
        for (int i = tid; i < 64 * 64; i += 256) {
            int r = i >> 6, c = i & 63;
            Ps[r][c] = p[(size_t)r * SEQ + kt * 64 + c];
            Vs[r][c] = vbase[(size_t)(kt * 64 + r) * E3 + c];
        }
        __syncthreads();
        #pragma unroll
        for (int k = 0; k < 64; k++) {
            float ra[4], rb[4];
            #pragma unroll
            for (int a = 0; a < 4; a++) ra[a] = Ps[ty + 16 * a][k];
            #pragma unroll
            for (int c = 0; c < 4; c++) rb[c] = Vs[k][tx + 16 * c];
            #pragma unroll
            for (int a = 0; a < 4; a++)
                #pragma unroll
                for (int c = 0; c < 4; c++) acc[a][c] += ra[a] * rb[c];
        }
        __syncthreads();
    }
    #pragma unroll
    for (int a = 0; a < 4; a++)
        #pragma unroll
        for (int c = 0; c < 4; c++)
            g_ao[((size_t)b * SEQ + qt * 64 + ty + 16 * a) * EMB
                 + head * HD + tx + 16 * c] = acc[a][c];
}

// ---------------- launch ----------------------------------------------------
extern "C" void kernel_launch(void* const* d_in, const int* in_sizes, int n_in,
                              void* d_out, int out_size) {
    const float* x      = (const float*)d_in[0];
    const float* w_qkv  = (const float*)d_in[1];
    const float* w_proj = (const float*)d_in[2];
    const int*   m_head  = (const int*)d_in[3];
    const int*   m_child = (const int*)d_in[4];

    float* out = (float*)d_out;
    const size_t out_elems = (size_t)BATCH * SEQ * EMB;
    const size_t arc_elems = (size_t)BATCH * MHEAD * SEQ * SEQ;
    float* arc = ((size_t)out_size >= out_elems + arc_elems)
                 ? out + out_elems : nullptr;

    float *p_qkv, *p_ao;
    cudaGetSymbolAddress((void**)&p_qkv, g_qkv);
    cudaGetSymbolAddress((void**)&p_ao,  g_ao);

    // 1) QKV = X @ Wqkv^T : [2048,3072]
    gemm_nt<64, 64, 16><<<dim3(E3 / 64, BATCH * SEQ / 64), 256>>>(
        x, w_qkv, p_qkv, BATCH * SEQ, E3, EMB);

    // 2) scores + mask + sigmoid side-output
    att_kernel<<<dim3(SEQ / 64, SEQ / 64, BATCH * MHEAD), 256>>>(
        m_head, m_child, arc);

    // 3) row softmax (in place)
    softmax_kernel<<<BATCH * MHEAD * SEQ, 256>>>();

    // 4) P @ V
    pv_kernel<<<dim3(SEQ / 64, BATCH * MHEAD), 256>>>();

    // 5) out = AO @ Wproj^T
    gemm_nt<64, 64, 16><<<dim3(EMB / 64, BATCH * SEQ / 64), 256>>>(
        p_ao, w_proj, out, BATCH * SEQ, EMB, EMB);
}

// round 5
// speedup vs baseline: 2.1066x; 2.1066x over previous
#include <cuda_runtime.h>
#include <cuda_bf16.h>
#include <math.h>
#include <stdint.h>

#define SEQ   1024
#define EMB   1024
#define BATCH 2
#define MHEAD 16      // total heads (M*H)
#define HD    64      // head dim
#define E3    (3*EMB)

// ---------------- scratch (allocation-free rule: __device__ globals) --------
__device__ float g_qkv[(size_t)BATCH*SEQ*E3];        // [2048][3072]  q|k|v
__device__ float g_att[(size_t)BATCH*MHEAD*SEQ*SEQ]; // att, then p in-place
__device__ float g_ao [(size_t)BATCH*SEQ*EMB];       // attention out pre-proj

// ===================== helpers ==============================================
__device__ __forceinline__ uint32_t smem_u32(const void* p) {
    uint32_t a;
    asm("{ .reg .u64 t; cvta.to.shared.u64 t, %1; cvt.u32.u64 %0, t; }"
        : "=r"(a) : "l"(p));
    return a;
}
__device__ __forceinline__ void ldsm4(uint32_t* r, uint32_t addr) {
    asm volatile("ldmatrix.sync.aligned.m8n8.x4.shared.b16 {%0,%1,%2,%3}, [%4];"
                 : "=r"(r[0]), "=r"(r[1]), "=r"(r[2]), "=r"(r[3]) : "r"(addr));
}
__device__ __forceinline__ void mma16816(float* d, const uint32_t* a,
                                         const uint32_t* b) {
    asm volatile("mma.sync.aligned.m16n8k16.row.col.f32.bf16.bf16.f32 "
                 "{%0,%1,%2,%3}, {%4,%5,%6,%7}, {%8,%9}, {%0,%1,%2,%3};"
                 : "+f"(d[0]), "+f"(d[1]), "+f"(d[2]), "+f"(d[3])
                 : "r"(a[0]), "r"(a[1]), "r"(a[2]), "r"(a[3]),
                   "r"(b[0]), "r"(b[1]));
}
__device__ __forceinline__ uint32_t pack_bf16(float x, float y) {
    __nv_bfloat162 p;
    p.x = __float2bfloat16(x);
    p.y = __float2bfloat16(y);
    return *(uint32_t*)&p;
}

// ========== bf16x3 NT GEMM via mma.sync: C[M][N] = A[M][K] @ B[N][K]^T ======
// Block tile 128x128, K-chunk 32. 8 warps: 4(m) x 2(n), warp tile 32x64.
// A,B fp32 K-major in gmem; split hi/lo bf16 in smem (row stride 40 bf16 =
// 80B, 16B-aligned & ldmatrix bank-conflict-free); 3 products hh+hl+lh.
#define PADK 40
__global__ void __launch_bounds__(256)
gemm_mma(const float* __restrict__ A, const float* __restrict__ B,
         float* __restrict__ C, int N, int K) {
    __shared__ __align__(16) __nv_bfloat16 sAh[128 * PADK], sAl[128 * PADK],
                                           sBh[128 * PADK], sBl[128 * PADK];
    const int tid = threadIdx.x, lane = tid & 31, wid = tid >> 5;
    const int wm = wid & 3, wn = wid >> 2;
    const int bm = blockIdx.y * 128, bn = blockIdx.x * 128;

    const uint32_t sb_ah = smem_u32(sAh), sb_al = smem_u32(sAl);
    const uint32_t sb_bh = smem_u32(sBh), sb_bl = smem_u32(sBl);

    float acc[2][8][4] = {};
    float2 av[8], bv[8];                    // gmem staging (software pipeline)

    auto load_stage = [&](int kt) {
        #pragma unroll
        for (int j = 0; j < 8; j++) {
            int idx = j * 256 + tid;        // float2 index; 16 float2 per row
            int row = idx >> 4, c2 = idx & 15;
            av[j] = *(const float2*)&A[(size_t)(bm + row) * K + kt + c2 * 2];
            bv[j] = *(const float2*)&B[(size_t)(bn + row) * K + kt + c2 * 2];
        }
    };
    auto store_stage = [&]() {
        #pragma unroll
        for (int j = 0; j < 8; j++) {
            int idx = j * 256 + tid;
            int row = idx >> 4, c2 = idx & 15;
            int off = row * PADK + c2 * 2;
            float ax = av[j].x, ay = av[j].y;
            uint32_t ah = pack_bf16(ax, ay);
            __nv_bfloat162* ahp = (__nv_bfloat162*)&ah;
            *(uint32_t*)&sAh[off] = ah;
            *(uint32_t*)&sAl[off] = pack_bf16(ax - __bfloat162float(ahp->x),
                                              ay - __bfloat162float(ahp->y));
            float bx = bv[j].x, by = bv[j].y;
            uint32_t bh = pack_bf16(bx, by);
            __nv_bfloat162* bhp = (__nv_bfloat162*)&bh;
            *(uint32_t*)&sBh[off] = bh;
            *(uint32_t*)&sBl[off] = pack_bf16(bx - __bfloat162float(bhp->x),
                                              by - __bfloat162float(bhp->y));
        }
    };

    const int nch = K / 32;
    load_stage(0);
    for (int ch = 0; ch < nch; ch++) {
        store_stage();
        __syncthreads();
        if (ch + 1 < nch) load_stage((ch + 1) * 32);

        #pragma unroll
        for (int ks = 0; ks < 2; ks++) {
            uint32_t ahf[2][4], alf[2][4];
            const int arow = wm * 32 + (lane & 15);
            const int acol = ks * 16 + (lane >> 4) * 8;
            #pragma unroll
            for (int mf = 0; mf < 2; mf++) {
                uint32_t ad = (uint32_t)(((arow + mf * 16) * PADK + acol) * 2);
                ldsm4(ahf[mf], sb_ah + ad);
                ldsm4(alf[mf], sb_al + ad);
            }
            const int brow = wn * 64 + ((lane >> 4) << 3) + (lane & 7);
            const int bcol = ks * 16 + ((lane >> 3) & 1) * 8;
            #pragma unroll
            for (int nf2 = 0; nf2 < 4; nf2++) {
                uint32_t bd = (uint32_t)(((brow + nf2 * 16) * PADK + bcol) * 2);
                uint32_t bhf[4], blf[4];
                ldsm4(bhf, sb_bh + bd);
                ldsm4(blf, sb_bl + bd);
                #pragma unroll
                for (int h = 0; h < 2; h++) {
                    #pragma unroll
                    for (int mf = 0; mf < 2; mf++) {
                        float* d = acc[mf][nf2 * 2 + h];
                        mma16816(d, ahf[mf], bhf + 2 * h);
                        mma16816(d, ahf[mf], blf + 2 * h);
                        mma16816(d, alf[mf], bhf + 2 * h);
                    }
                }
            }
        }
        __syncthreads();
    }

    // epilogue: fragment layout -> gmem
    #pragma unroll
    for (int mf = 0; mf < 2; mf++) {
        const int r = bm + wm * 32 + mf * 16 + (lane >> 2);
        #pragma unroll
        for (int nf = 0; nf < 8; nf++) {
            const int c = bn + wn * 64 + nf * 8 + (lane & 3) * 2;
            *(float2*)&C[(size_t)r * N + c] =
                make_float2(acc[mf][nf][0], acc[mf][nf][1]);
            *(float2*)&C[(size_t)(r + 8) * N + c] =
                make_float2(acc[mf][nf][2], acc[mf][nf][3]);
        }
    }
}

// ---------------- scores: att = mask(QK^T/64); arc = sigmoid(att) -----------
// grid: (S/64 key tiles, S/64 query tiles, B*MHEAD)
__global__ void att_kernel(const int* __restrict__ mask_head,
                           const int* __restrict__ mask_child,
                           float* __restrict__ arc) {
    const int bh   = blockIdx.z;          // b*16 + head
    const int b    = bh >> 4;
    const int head = bh & 15;
    const int grp  = head >> 3;           // 0 -> mask_head, 1 -> mask_child
    const int q0 = blockIdx.y * 64, k0 = blockIdx.x * 64;
    const int tid = threadIdx.x;
    const int tx = tid & 15, ty = tid >> 4;

    float* attp = g_att + (size_t)bh * SEQ * SEQ;
    float* arcp = arc ? arc + (size_t)bh * SEQ * SEQ : nullptr;

    if (k0 > q0 + 63) {  // fully above causal diagonal
        #pragma unroll
        for (int a = 0; a < 4; a++)
            #pragma unroll
            for (int c = 0; c < 4; c++) {
                size_t idx = (size_t)(q0 + ty + 16 * a) * SEQ + (k0 + tx + 16 * c);
                attp[idx] = -INFINITY;
                if (arcp) arcp[idx] = 0.0f;
            }
        return;
    }

    __shared__ float Qs[HD][65];
    __shared__ float Ks[HD][65];
    const float* qbase = g_qkv + ((size_t)b * SEQ + q0) * E3 + head * HD;
    const float* kbase = g_qkv + ((size_t)b * SEQ + k0) * E3 + EMB + head * HD;
    #pragma unroll
    for (int i = tid; i < 64 * HD; i += 256) {
        int r = i >> 6, c = i & 63;
        Qs[c][r] = qbase[(size_t)r * E3 + c];
        Ks[c][r] = kbase[(size_t)r * E3 + c];
    }
    __syncthreads();

    float acc[4][4] = {};
    #pragma unroll
    for (int k = 0; k < HD; k++) {
        float ra[4], rb[4];
        #pragma unroll
        for (int a = 0; a < 4; a++) ra[a] = Qs[k][ty + 16 * a];
        #pragma unroll
        for (int c = 0; c < 4; c++) rb[c] = Ks[k][tx + 16 * c];
        #pragma unroll
        for (int a = 0; a < 4; a++)
            #pragma unroll
            for (int c = 0; c < 4; c++) acc[a][c] += ra[a] * rb[c];
    }

    const int* msk = (grp == 0 ? mask_head : mask_child) + (size_t)b * SEQ * SEQ;
    #pragma unroll
    for (int a = 0; a < 4; a++) {
        int qi = q0 + ty + 16 * a;
        #pragma unroll
        for (int c = 0; c < 4; c++) {
            int kj = k0 + tx + 16 * c;
            float val = acc[a][c] * (1.0f / 64.0f);   // scaled twice by d^-0.5
            bool valid = (kj <= qi) && (msk[(size_t)qi * SEQ + kj] != 0);
            size_t idx = (size_t)qi * SEQ + kj;
            attp[idx] = valid ? val : -INFINITY;
            if (arcp) arcp[idx] = valid ? 1.0f / (1.0f + __expf(-val)) : 0.0f;
        }
    }
}

// ---------------- softmax over rows (in-place on g_att) ---------------------
__global__ void softmax_kernel() {
    const int row = blockIdx.x;                // 0..B*MHEAD*SEQ-1
    float* p = g_att + (size_t)row * SEQ;
    const int tid = threadIdx.x;               // 256
    float v[4];
    float mx = -INFINITY;
    #pragma unroll
    for (int i = 0; i < 4; i++) { v[i] = p[tid + 256 * i]; mx = fmaxf(mx, v[i]); }
    __shared__ float red[256];
    red[tid] = mx; __syncthreads();
    for (int s = 128; s > 0; s >>= 1) {
        if (tid < s) red[tid] = fmaxf(red[tid], red[tid + s]);
        __syncthreads();
    }
    mx = red[0]; __syncthreads();
    if (mx == -INFINITY) {                     // fully-masked row (defensive)
        #pragma unroll
        for (int i = 0; i < 4; i++) p[tid + 256 * i] = 0.0f;
        return;
    }
    float sum = 0.0f;
    #pragma unroll
    for (int i = 0; i < 4; i++) { v[i] = __expf(v[i] - mx); sum += v[i]; }
    red[tid] = sum; __syncthreads();
    for (int s = 128; s > 0; s >>= 1) {
        if (tid < s) red[tid] += red[tid + s];
        __syncthreads();
    }
    float inv = 1.0f / red[0];
    #pragma unroll
    for (int i = 0; i < 4; i++) p[tid + 256 * i] = v[i] * inv;
}

// ---------------- PV: ao[b,q,head*64+c] = sum_k p[q,k] * v[k,c] -------------
// grid: (S/64 query tiles, B*MHEAD). Causal: only K tiles kt <= qt contribute.
__global__ void pv_kernel() {
    const int bh = blockIdx.y;
    const int b = bh >> 4, head = bh & 15;
    const int qt = blockIdx.x;
    const int tid = threadIdx.x;
    const int tx = tid & 15, ty = tid >> 4;

    const float* p = g_att + (size_t)bh * SEQ * SEQ + (size_t)qt * 64 * SEQ;
    const float* vbase = g_qkv + (size_t)b * SEQ * E3 + 2 * EMB + head * HD;

    __shared__ float Ps[64][65];
    __shared__ float Vs[64][65];
    float acc[4][4] = {};
    for (int kt = 0; kt <= qt; kt++) {
        #pragma unroll
        for (int i = tid; i < 64 * 64; i += 256) {
            int r = i >> 6, c = i & 63;
            Ps[r][c] = p[(size_t)r * SEQ + kt * 64 + c];
            Vs[r][c] = vbase[(size_t)(kt * 64 + r) * E3 + c];
        }
        __syncthreads();
        #pragma unroll
        for (int k = 0; k < 64; k++) {
            float ra[4], rb[4];
            #pragma unroll
            for (int a = 0; a < 4; a++) ra[a] = Ps[ty + 16 * a][k];
            #pragma unroll
            for (int c = 0; c < 4; c++) rb[c] = Vs[k][tx + 16 * c];
            #pragma unroll
            for (int a = 0; a < 4; a++)
                #pragma unroll
                for (int c = 0; c < 4; c++) acc[a][c] += ra[a] * rb[c];
        }
        __syncthreads();
    }
    #pragma unroll
    for (int a = 0; a < 4; a++)
        #pragma unroll
        for (int c = 0; c < 4; c++)
            g_ao[((size_t)b * SEQ + qt * 64 + ty + 16 * a) * EMB
                 + head * HD + tx + 16 * c] = acc[a][c];
}

// ---------------- launch ----------------------------------------------------
extern "C" void kernel_launch(void* const* d_in, const int* in_sizes, int n_in,
                              void* d_out, int out_size) {
    const float* x      = (const float*)d_in[0];
    const float* w_qkv  = (const float*)d_in[1];
    const float* w_proj = (const float*)d_in[2];
    const int*   m_head  = (const int*)d_in[3];
    const int*   m_child = (const int*)d_in[4];

    float* out = (float*)d_out;
    const size_t out_elems = (size_t)BATCH * SEQ * EMB;
    const size_t arc_elems = (size_t)BATCH * MHEAD * SEQ * SEQ;
    float* arc = ((size_t)out_size >= out_elems + arc_elems)
                 ? out + out_elems : nullptr;

    float *p_qkv, *p_ao;
    cudaGetSymbolAddress((void**)&p_qkv, g_qkv);
    cudaGetSymbolAddress((void**)&p_ao,  g_ao);

    // 1) QKV = X @ Wqkv^T : [2048,3072]  (bf16x3 mma.sync)
    gemm_mma<<<dim3(E3 / 128, BATCH * SEQ / 128), 256>>>(
        x, w_qkv, p_qkv, E3, EMB);

    // 2) scores + mask + sigmoid side-output
    att_kernel<<<dim3(SEQ / 64, SEQ / 64, BATCH * MHEAD), 256>>>(
        m_head, m_child, arc);

    // 3) row softmax (in place)
    softmax_kernel<<<BATCH * MHEAD * SEQ, 256>>>();

    // 4) P @ V
    pv_kernel<<<dim3(SEQ / 64, BATCH * MHEAD), 256>>>();

    // 5) out = AO @ Wproj^T  (bf16x3 mma.sync)
    gemm_mma<<<dim3(EMB / 128, BATCH * SEQ / 128), 256>>>(
        p_ao, w_proj, out, EMB, EMB);
}